// round 1
// baseline (speedup 1.0000x reference)
#include <cuda_runtime.h>
#include <cuda_bf16.h>

// Problem shape (fixed by the dataset): x = (N=2, C=16, D=96, H=128, W=128) fp32
// Output: concat(gx, gy, gz), each same shape as x.

#define W_   128
#define H_   128
#define D_   96
#define NC_  32          // N*C = 2*16
#define TY_  8           // y-rows per block
#define SMW_ 132         // padded smem row (W+2 -> 132 for alignment)

__global__ __launch_bounds__(1024, 1)
void sobel3d_kernel(const float* __restrict__ in, float* __restrict__ out) {
    __shared__ float sm[2][TY_ + 2][SMW_];

    const int tx  = threadIdx.x;           // 0..127 (x position)
    const int ty  = threadIdx.y;           // 0..7
    const int tid = ty * W_ + tx;          // 0..1023
    const int y0  = blockIdx.x * TY_;      // y-tile origin
    const int nc  = blockIdx.y;            // which (n,c) plane stack

    const long long HW = (long long)H_ * W_;
    const float* src = in + (long long)nc * D_ * HW;
    const long long V = (long long)NC_ * D_ * HW;  // elements per output tensor
    float* gx = out;
    float* gy = out + V;
    float* gz = out + 2 * V;

    const long long obase = (long long)nc * D_ * HW + (long long)(y0 + ty) * W_ + tx;

    // z-direction register rings: values at z-2 (m) and z-1 (0)
    float am = 0.f, a0 = 0.f;
    float bm = 0.f, b0 = 0.f;
    float cm = 0.f, c0 = 0.f;

    for (int zp = 0; zp < D_; ++zp) {
        const int p = zp & 1;
        const float* plane = src + (long long)zp * HW;

        // Load plane zp: rows y0-1 .. y0+TY_, cols -1 .. W (zero-padded), coalesced.
        #pragma unroll
        for (int i = tid; i < (TY_ + 2) * (W_ + 2); i += TY_ * W_) {
            int row = i / (W_ + 2);
            int col = i - row * (W_ + 2);
            int gyy = y0 - 1 + row;
            int gxx = col - 1;
            float v = 0.f;
            if ((unsigned)gyy < (unsigned)H_ && (unsigned)gxx < (unsigned)W_)
                v = plane[gyy * W_ + gxx];
            sm[p][row][col] = v;
        }
        __syncthreads();

        // Per-plane 2D separable partials at this thread's (y,x):
        //   A = smooth_y * deriv_x,  B = deriv_y * smooth_x,  C = smooth_y * smooth_x
        const int r = ty + 1, c = tx + 1;
        float ap, bp, cp;
        {
            float l0 = sm[p][r - 1][c - 1], m0 = sm[p][r - 1][c], r0 = sm[p][r - 1][c + 1];
            float l1 = sm[p][r    ][c - 1], m1 = sm[p][r    ][c], r1 = sm[p][r    ][c + 1];
            float l2 = sm[p][r + 1][c - 1], m2 = sm[p][r + 1][c], r2 = sm[p][r + 1][c + 1];
            float d0 = r0 - l0;
            float d1 = r1 - l1;
            float d2 = r2 - l2;
            float s0 = l0 + 2.f * m0 + r0;
            float s1 = l1 + 2.f * m1 + r1;
            float s2 = l2 + 2.f * m2 + r2;
            ap = d0 + 2.f * d1 + d2;   // smooth over y of deriv_x
            bp = s2 - s0;              // deriv over y of smooth_x
            cp = s0 + 2.f * s1 + s2;   // smooth over y of smooth_x
        }

        // With plane zp's partials ready, output plane zp-1 is complete.
        if (zp >= 1) {
            long long o = obase + (long long)(zp - 1) * HW;
            gx[o] = am + 2.f * a0 + ap;
            gy[o] = bm + 2.f * b0 + bp;
            gz[o] = cp - cm;
        }
        am = a0; a0 = ap;
        bm = b0; b0 = bp;
        cm = c0; c0 = cp;
    }

    // Final plane z = D-1 (plane D is zero padding).
    {
        long long o = obase + (long long)(D_ - 1) * HW;
        gx[o] = am + 2.f * a0;
        gy[o] = bm + 2.f * b0;
        gz[o] = -cm;
    }
}

extern "C" void kernel_launch(void* const* d_in, const int* in_sizes, int n_in,
                              void* d_out, int out_size) {
    const float* x = (const float*)d_in[0];
    float* out = (float*)d_out;

    dim3 block(W_, TY_, 1);              // 1024 threads
    dim3 grid(H_ / TY_, NC_, 1);         // 16 x 32 = 512 blocks
    sobel3d_kernel<<<grid, block>>>(x, out);
}

// round 2
// speedup vs baseline: 3.6803x; 3.6803x over previous
#include <cuda_runtime.h>
#include <cuda_bf16.h>

// x = (N=2, C=16, D=96, H=128, W=128) fp32; out = concat(gx, gy, gz).

#define W_   128
#define H_   128
#define D_   96
#define NC_  32
#define YT_  8     // rows (warps) per block
#define ZC_  24    // z outputs per block

__device__ __forceinline__ float4 ld4z(const float* p, bool ok) {
    if (ok) {
        return *reinterpret_cast<const float4*>(p);
    }
    return make_float4(0.f, 0.f, 0.f, 0.f);
}

__global__ __launch_bounds__(256, 4)
void sobel3d_kernel(const float* __restrict__ in, float* __restrict__ out) {
    const int lane = threadIdx.x;             // 0..31
    const int y    = blockIdx.x * YT_ + threadIdx.y;
    const int z0   = blockIdx.y * ZC_;
    const int nc   = blockIdx.z;
    const int x4   = lane * 4;

    const long long HW = (long long)H_ * W_;
    const float* src = in + (long long)nc * D_ * HW;
    const long long V = (long long)NC_ * D_ * HW;
    float* gx = out;
    float* gy = out + V;
    float* gz = out + 2 * V;

    const bool ym_ok = (y > 0);
    const bool yp_ok = (y < H_ - 1);
    const int roff_m = (y - 1) * W_ + x4;
    const int roff_0 = y * W_ + x4;
    const int roff_p = (y + 1) * W_ + x4;

    // z register rings for the three per-plane partials
    float4 am = make_float4(0,0,0,0), a0 = am;
    float4 bm = am, b0 = am;
    float4 cm = am, c0 = am;

    #pragma unroll 2
    for (int pz = z0 - 1; pz <= z0 + ZC_; ++pz) {
        const bool zin = (pz >= 0) && (pz < D_);
        const float* plane = src + (long long)pz * HW;

        float4 rm = ld4z(plane + roff_m, zin && ym_ok);
        float4 r0 = ld4z(plane + roff_0, zin);
        float4 rp = ld4z(plane + roff_p, zin && yp_ok);

        // vertical (y) combos
        float4 d, s;
        d.x = rp.x - rm.x; d.y = rp.y - rm.y; d.z = rp.z - rm.z; d.w = rp.w - rm.w;
        s.x = rm.x + 2.f*r0.x + rp.x;
        s.y = rm.y + 2.f*r0.y + rp.y;
        s.z = rm.z + 2.f*r0.z + rp.z;
        s.w = rm.w + 2.f*r0.w + rp.w;

        // horizontal halo via shuffles (row is exactly one warp wide)
        float sL = __shfl_up_sync(0xffffffffu, s.w, 1);
        float sR = __shfl_down_sync(0xffffffffu, s.x, 1);
        float dL = __shfl_up_sync(0xffffffffu, d.w, 1);
        float dR = __shfl_down_sync(0xffffffffu, d.x, 1);
        if (lane == 0)  { sL = 0.f; dL = 0.f; }
        if (lane == 31) { sR = 0.f; dR = 0.f; }

        // per-plane partials:
        //   a = deriv_x(smooth_y), b = smooth_x(deriv_y), c = smooth_x(smooth_y)
        float4 ap, bp, cp;
        ap.x = s.y - sL;  ap.y = s.z - s.x;  ap.z = s.w - s.y;  ap.w = sR - s.z;
        bp.x = dL + 2.f*d.x + d.y;
        bp.y = d.x + 2.f*d.y + d.z;
        bp.z = d.y + 2.f*d.z + d.w;
        bp.w = d.z + 2.f*d.w + dR;
        cp.x = sL + 2.f*s.x + s.y;
        cp.y = s.x + 2.f*s.y + s.z;
        cp.z = s.y + 2.f*s.z + s.w;
        cp.w = s.z + 2.f*s.w + sR;

        const int oz = pz - 1;
        if (oz >= z0) {   // oz < z0+ZC_ guaranteed by loop bound
            const long long o = (long long)nc * D_ * HW + (long long)oz * HW + roff_0;
            float4 vx, vy, vz;
            vx.x = am.x + 2.f*a0.x + ap.x;
            vx.y = am.y + 2.f*a0.y + ap.y;
            vx.z = am.z + 2.f*a0.z + ap.z;
            vx.w = am.w + 2.f*a0.w + ap.w;
            vy.x = bm.x + 2.f*b0.x + bp.x;
            vy.y = bm.y + 2.f*b0.y + bp.y;
            vy.z = bm.z + 2.f*b0.z + bp.z;
            vy.w = bm.w + 2.f*b0.w + bp.w;
            vz.x = cp.x - cm.x; vz.y = cp.y - cm.y;
            vz.z = cp.z - cm.z; vz.w = cp.w - cm.w;
            *reinterpret_cast<float4*>(gx + o) = vx;
            *reinterpret_cast<float4*>(gy + o) = vy;
            *reinterpret_cast<float4*>(gz + o) = vz;
        }
        am = a0; a0 = ap;
        bm = b0; b0 = bp;
        cm = c0; c0 = cp;
    }
}

extern "C" void kernel_launch(void* const* d_in, const int* in_sizes, int n_in,
                              void* d_out, int out_size) {
    const float* x = (const float*)d_in[0];
    float* out = (float*)d_out;

    dim3 block(32, YT_, 1);                  // 256 threads
    dim3 grid(H_ / YT_, D_ / ZC_, NC_);      // 16 x 4 x 32 = 2048 blocks
    sobel3d_kernel<<<grid, block>>>(x, out);
}